// round 15
// baseline (speedup 1.0000x reference)
#include <cuda_runtime.h>

#define BB 32
#define TT 512
#define UU 512
#define NG 1536          // 3*U
#define OC 1024          // 2*U output channels

// per-step rh = r * h_prev exchange buffer
__device__ float    g_rh[2 * BB * UU];
// per-step split barriers (reset at kernel end, replay-safe)
__device__ int      g_bar1[2 * TT];
__device__ int      g_bar2[2 * TT];
__device__ int      g_done;

__device__ __forceinline__ float hsig(float v) {
    return fminf(fmaxf(0.2f * v + 0.5f, 0.0f), 1.0f);
}

// consumer-only named barrier (warps 0-7, 256 threads)
#define BAR_CONS() asm volatile("bar.sync 1, 256;" ::: "memory")

__device__ __forceinline__ void bar_arrive_cons(int* cnt, int tid)
{
    __threadfence();                 // release consumer global writes
    BAR_CONS();                      // all consumer threads fenced
    if (tid == 0) atomicAdd(cnt, 1);
}

__device__ __forceinline__ void bar_wait_cons(int* cnt, int tid)
{
    if (tid == 0) {
        while (*(volatile int*)cnt < 64) { }
        __threadfence();             // acquire
    }
    BAR_CONS();
}

// ---------------------------------------------------------------------------
// Fused persistent kernel. 128 blocks x 512 threads (1 block/SM).
//   warps 0-7  (tid 0..255)  : consumers — GRU scan, r12 mapping + r14
//                              split-phase bar1 hiding, grid barriers.
//   warps 8-15 (tid 256..511): producers — compute this block's own 24
//                              x-gate columns for step s+1 into smem ring.
// Handoff: one full-block __syncthreads per step (ring phase flip).
// smem floats: sW 12288 | sH 16416 | red 2048 | xbuf 1536 | sWin 12288
//            = 44576 floats = 178,304 B
// ---------------------------------------------------------------------------
#define SCAN_SMEM_FLOATS (12288 + 16416 + 2048 + 1536 + 12288)
#define SCAN_SMEM_BYTES  (SCAN_SMEM_FLOATS * 4)

__global__ void __launch_bounds__(512, 1)
scan_kernel(const float* __restrict__ x,
            const float* __restrict__ Wf, const float* __restrict__ Uf,
            const float* __restrict__ bf,
            const float* __restrict__ Wb, const float* __restrict__ Ub,
            const float* __restrict__ bb,
            float* __restrict__ out)
{
    extern __shared__ float sm[];
    float* sW   = sm;              // recurrent U slice [g][u][c] : g*4096+u*8+c
    float* sH   = sm + 12288;      // h staging [b][u] : b*513 + u
    float* red  = sH + 16416;      // reduction scratch (4 ks x 32 b x 2 x 8 c)
    float* xbuf = red + 2048;      // ring: ph*768 + g*256 + b*8 + c
    float* sWin = xbuf + 1536;     // input W slice [g][u][c] (producers)

    const int tid   = threadIdx.x;
    const int dir   = blockIdx.x >> 6;
    const int cg    = blockIdx.x & 63;
    const int hbase = cg << 3;
    const float* __restrict__ Urec = dir ? Ub : Uf;
    const float* __restrict__ Win  = dir ? Wb : Wf;
    const float* __restrict__ bias = dir ? bb : bf;

    // --- both weight slices, loaded ONCE by all 512 threads ---
    for (int i = tid; i < 12288; i += 512) {
        const int c = i & 7;
        const int u = (i >> 3) & 511;
        const int g = i >> 12;
        const size_t col = (size_t)g * UU + hbase + c;
        sW[i]   = Urec[(size_t)u * NG + col];
        sWin[i] = Win [(size_t)u * NG + col];
    }
    __syncthreads();

    int* __restrict__ bar1 = g_bar1 + dir * TT;
    int* __restrict__ bar2 = g_bar2 + dir * TT;
    const int rh_base = (dir * BB) << 9;

    if (tid >= 256) {
        // =================== PRODUCER WARPS (8..15) =======================
        const int tid2 = tid - 256;
        const int pb = tid2 >> 3;          // 0..31 batch
        const int pc = tid2 & 7;           // 0..7  column
        const float bz = bias[hbase + pc];
        const float br = bias[UU + hbase + pc];
        const float bh = bias[2 * UU + hbase + pc];
        const float* __restrict__ wz = sWin + pc;            // [u*8] stride
        const float* __restrict__ wr = sWin + 4096 + pc;
        const float* __restrict__ wh = sWin + 8192 + pc;

        // produce tile for step sp into xbuf[sp&1]
        auto produce = [&](int sp) {
            const int t_x = dir ? (TT - 1 - sp) : sp;
            const float4* __restrict__ xrow =
                (const float4*)(x + ((size_t)pb * TT + t_x) * UU);
            float az = 0.f, ar = 0.f, ah = 0.f;
#pragma unroll 4
            for (int u4 = 0; u4 < 128; ++u4) {
                const float4 xv = __ldg(xrow + u4);
                const int ub = u4 << 5;                       // (4u)*8
                az = fmaf(xv.x, wz[ub],      az);
                ar = fmaf(xv.x, wr[ub],      ar);
                ah = fmaf(xv.x, wh[ub],      ah);
                az = fmaf(xv.y, wz[ub + 8],  az);
                ar = fmaf(xv.y, wr[ub + 8],  ar);
                ah = fmaf(xv.y, wh[ub + 8],  ah);
                az = fmaf(xv.z, wz[ub + 16], az);
                ar = fmaf(xv.z, wr[ub + 16], ar);
                ah = fmaf(xv.z, wh[ub + 16], ah);
                az = fmaf(xv.w, wz[ub + 24], az);
                ar = fmaf(xv.w, wr[ub + 24], ar);
                ah = fmaf(xv.w, wh[ub + 24], ah);
            }
            float* dst = xbuf + (sp & 1) * 768 + pb * 8 + pc;
            dst[0]   = az + bz;
            dst[256] = ar + br;
            dst[512] = ah + bh;
        };

        produce(0);                        // prime tile 0
        __syncthreads();                   // handoff (init)

        for (int s = 0; s < TT; ++s) {
            if (s + 1 < TT) produce(s + 1);
            __syncthreads();               // end-of-step handoff
        }
    } else {
        // =================== CONSUMER WARPS (0..7) ========================
        // GEMM mapping (r12): 4 ks x 8 bg x 8 c
        const int ks = tid >> 6;           // 0..3 (K quarter)
        const int bg = (tid >> 3) & 7;     // 0..7 (batch group of 4)
        const int c  = tid & 7;            // 0..7
        const int u0 = ks << 7;
        // reduce mapping
        const int rb = tid >> 3;           // 0..31
        const int rc = tid & 7;            // 0..7
        const int j  = hbase + rc;

        const float* __restrict__ pw = sW + (u0 << 3) + c;
        const float* __restrict__ h0 = sH + (bg * 4 + 0) * 513 + u0;
        const float* __restrict__ h1 = h0 + 513;
        const float* __restrict__ h2 = h1 + 513;
        const float* __restrict__ h3 = h2 + 513;

        __syncthreads();                   // match producer's init handoff

        for (int s = 0; s < TT; ++s) {
            // x-gate values from smem ring (produced during step s-1)
            const float* xb = xbuf + (s & 1) * 768 + rb * 8 + rc;
            const float xz = xb[0];
            const float xr = xb[256];
            const float xh = xb[512];

            // ---- stage h_prev into sH (16 float4 per thread) ----
            if (s == 0) {
                for (int i = tid; i < 16416; i += 256) sH[i] = 0.0f;
            } else {
                const float* __restrict__ hp_base =
                    out + (size_t)(s - 1) * OC + (size_t)dir * UU;
#pragma unroll 4
                for (int i = tid; i < 4096; i += 256) {
                    const int b  = i >> 7;
                    const int u4 = (i & 127) << 2;
                    float4 v = __ldcg((const float4*)(hp_base +
                                      (size_t)b * TT * OC + u4));
                    float* d = sH + b * 513 + u4;
                    d[0] = v.x; d[1] = v.y; d[2] = v.z; d[3] = v.w;
                }
            }
            BAR_CONS();

            const float hp = sH[rb * 513 + j];

            // ---- phase A-r: r-gate GEMM ----
            float ar0 = 0.f, ar1 = 0.f, ar2 = 0.f, ar3 = 0.f;
#pragma unroll 8
            for (int uu = 0; uu < 128; ++uu) {
                const float wr = pw[uu * 8 + 4096];
                ar0 = fmaf(h0[uu], wr, ar0);
                ar1 = fmaf(h1[uu], wr, ar1);
                ar2 = fmaf(h2[uu], wr, ar2);
                ar3 = fmaf(h3[uu], wr, ar3);
            }
            {
                float* rp = red + ks * 256 + (bg * 4) * 8 + c;
                rp[0]  = ar0;
                rp[8]  = ar1;
                rp[16] = ar2;
                rp[24] = ar3;
            }
            BAR_CONS();
            {
                const float* rr = red + rb * 8 + rc;
                const float hr = rr[0] + rr[256] + rr[512] + rr[768];
                const float r  = hsig(xr + hr);
                g_rh[rh_base + (rb << 9) + j] = r * hp;
            }
            bar_arrive_cons(&bar1[s], tid);   // rh published

            // ---- phase A-z: z-gate GEMM (overlaps bar1 arrivals) ----
            float az0 = 0.f, az1 = 0.f, az2 = 0.f, az3 = 0.f;
#pragma unroll 8
            for (int uu = 0; uu < 128; ++uu) {
                const float wz = pw[uu * 8];
                az0 = fmaf(h0[uu], wz, az0);
                az1 = fmaf(h1[uu], wz, az1);
                az2 = fmaf(h2[uu], wz, az2);
                az3 = fmaf(h3[uu], wz, az3);
            }
            {
                float* rp = red + ks * 256 + (bg * 4) * 8 + c;
                rp[0]  = az0;
                rp[8]  = az1;
                rp[16] = az2;
                rp[24] = az3;
            }
            BAR_CONS();
            float rz = 0.0f, rzh = 0.0f;
            {
                const float* rr = red + rb * 8 + rc;
                const float hz = rr[0] + rr[256] + rr[512] + rr[768];
                const float z  = hsig(xz + hz);
                rz  = z;
                rzh = z * hp;
            }
            bar_wait_cons(&bar1[s], tid);     // nearly free by now

            // ---- stage rh into sH ----
#pragma unroll 4
            for (int i = tid; i < 4096; i += 256) {
                const int b  = i >> 7;
                const int u4 = (i & 127) << 2;
                float4 v = __ldcg((const float4*)(g_rh + rh_base +
                                                  (b << 9) + u4));
                float* d = sH + b * 513 + u4;
                d[0] = v.x; d[1] = v.y; d[2] = v.z; d[3] = v.w;
            }
            BAR_CONS();

            // ---- phase B: candidate GEMM ----
            float ah0 = 0.f, ah1 = 0.f, ah2 = 0.f, ah3 = 0.f;
#pragma unroll 8
            for (int uu = 0; uu < 128; ++uu) {
                const float wh = pw[uu * 8 + 8192];
                ah0 = fmaf(h0[uu], wh, ah0);
                ah1 = fmaf(h1[uu], wh, ah1);
                ah2 = fmaf(h2[uu], wh, ah2);
                ah3 = fmaf(h3[uu], wh, ah3);
            }
            {
                float* rp = red + ks * 256 + (bg * 4) * 8 + c;
                rp[0]  = ah0;
                rp[8]  = ah1;
                rp[16] = ah2;
                rp[24] = ah3;
            }
            BAR_CONS();
            {
                const float* rr = red + rb * 8 + rc;
                const float hh   = rr[0] + rr[256] + rr[512] + rr[768];
                const float cand = tanhf(xh + hh);
                const float hnew = rzh + (1.0f - rz) * cand;
                out[((size_t)rb * TT + s) * OC + (size_t)dir * UU + j] = hnew;
            }

            // ---- step closure ----
            bar_arrive_cons(&bar2[s], tid);
            bar_wait_cons(&bar2[s], tid);

            __syncthreads();               // end-of-step handoff (all 512)
        }
    }

    // ---- reset per-step counters for next graph replay ----
    __syncthreads();
    if (tid == 0) atomicAdd(&g_done, 1);
    if (blockIdx.x == 0) {
        if (tid == 0) {
            while (*(volatile int*)&g_done < 128) { }
        }
        __syncthreads();
        for (int i = tid; i < 2 * TT; i += 512) {
            g_bar1[i] = 0;
            g_bar2[i] = 0;
        }
        __threadfence();
        __syncthreads();
        if (tid == 0) g_done = 0;
    }
}

// ---------------------------------------------------------------------------
extern "C" void kernel_launch(void* const* d_in, const int* in_sizes, int n_in,
                              void* d_out, int out_size)
{
    (void)in_sizes; (void)n_in; (void)out_size;
    const float* x  = (const float*)d_in[0];
    const float* Wf = (const float*)d_in[1];
    const float* Uf = (const float*)d_in[2];
    const float* bf = (const float*)d_in[3];
    const float* Wb = (const float*)d_in[4];
    const float* Ub = (const float*)d_in[5];
    const float* bb = (const float*)d_in[6];
    float* out = (float*)d_out;

    cudaFuncSetAttribute(scan_kernel,
                         cudaFuncAttributeMaxDynamicSharedMemorySize,
                         SCAN_SMEM_BYTES);

    scan_kernel<<<128, 512, SCAN_SMEM_BYTES>>>(x, Wf, Uf, bf, Wb, Ub, bb, out);
}